// round 3
// baseline (speedup 1.0000x reference)
#include <cuda_runtime.h>
#include <math.h>

// Problem constants (shapes are fixed for this problem instance)
#define NN 100000
#define NE 1000000

// ---------------- scratch (static device globals; no allocation) ----------
__device__ float g_xl  [NN * 64];   // x @ W_l
__device__ float g_agg [NN * 64];   // segment_sum(xl[row]) into col
__device__ float g_cnt [NN];        // in-degree
__device__ float g_sout[NN];        // dot(out[n], W_att[0:64])
__device__ float g_sums[128];       // [0:64) sum, [64:128) sumsq
__device__ float2 g_coef[64];       // fused BN*2 scale/shift

// ---------------- K0: zero scratch ----------------------------------------
__global__ void zero_kernel(int n_agg, int n_cnt) {
    int i = blockIdx.x * blockDim.x + threadIdx.x;
    if (i < n_agg) g_agg[i] = 0.0f;
    if (i < n_cnt) g_cnt[i] = 0.0f;
    if (i < 128)   g_sums[i] = 0.0f;
}

// ---------------- K1: fused node GEMM: xl = x@W_l, out = x@W_r ------------
// Combined weight tile Wc[128][128] in smem (cols 0..63 = W_l, 64..127 = W_r).
// One warp computes 8 rows; per k: one LDS.128 of W amortized over 8 rows
// (32 FMAs) -> FMA-bound, not smem-bound.
__global__ void node_gemm_kernel(const float* __restrict__ x,
                                 const float* __restrict__ Wl,
                                 const float* __restrict__ Wr,
                                 float* __restrict__ out, int N) {
    extern __shared__ float sm[];
    float* Wc = sm;                                   // 128*128 floats = 64KB
    const int tid  = threadIdx.x;
    const int lane = tid & 31;
    const int wid  = tid >> 5;
    float* xs = sm + 128 * 128 + wid * (8 * 128);     // 8 rows x 128 per warp

    for (int i = tid; i < 128 * 64; i += blockDim.x) {
        int k = i >> 6, j = i & 63;
        Wc[k * 128 + j]      = Wl[i];
        Wc[k * 128 + 64 + j] = Wr[i];
    }
    __syncthreads();

    int base = (blockIdx.x * 8 + wid) * 8;            // N % 8 == 0
    if (base >= N) return;

    // stage this warp's 8 rows of x (1024 floats) into smem
    const float4* xg = (const float4*)(x + (size_t)base * 128);
    #pragma unroll
    for (int i = 0; i < 8; i++)
        ((float4*)xs)[lane + 32 * i] = xg[lane + 32 * i];
    __syncwarp();

    float4 acc[8];
    #pragma unroll
    for (int r = 0; r < 8; r++) acc[r] = make_float4(0.f, 0.f, 0.f, 0.f);

    #pragma unroll 4
    for (int k = 0; k < 128; k++) {
        float4 wv = *(const float4*)(Wc + k * 128 + lane * 4);
        #pragma unroll
        for (int r = 0; r < 8; r++) {
            float xk = xs[r * 128 + k];
            acc[r].x = fmaf(xk, wv.x, acc[r].x);
            acc[r].y = fmaf(xk, wv.y, acc[r].y);
            acc[r].z = fmaf(xk, wv.z, acc[r].z);
            acc[r].w = fmaf(xk, wv.w, acc[r].w);
        }
    }

    #pragma unroll
    for (int r = 0; r < 8; r++) {
        int row = base + r;
        if (lane < 16) ((float4*)(g_xl + (size_t)row * 64))[lane]      = acc[r];
        else           ((float4*)(out  + (size_t)row * 64))[lane - 16] = acc[r];
    }
}

// ---------------- K2: edge aggregation: agg[col] += xl[row], cnt[col]++ ---
// 16 lanes per edge, float4 per lane, vectorized red (L2-resident targets).
__global__ void edge_agg_kernel(const int* __restrict__ ei, int E) {
    int t = blockIdx.x * blockDim.x + threadIdx.x;
    int e = t >> 4;
    if (e >= E) return;
    int l = t & 15;
    int r = __ldg(ei + e);
    int c = __ldg(ei + E + e);
    float4 v = ((const float4*)(g_xl + (size_t)r * 64))[l];
    float* dst = g_agg + (size_t)c * 64 + l * 4;
    asm volatile("red.global.add.v4.f32 [%0], {%1,%2,%3,%4};"
                 :: "l"(dst), "f"(v.x), "f"(v.y), "f"(v.z), "f"(v.w)
                 : "memory");
    if (l == 0) atomicAdd(g_cnt + c, 1.0f);
}

// ---------------- K3: out = agg/max(cnt,1) + x@W_r + b_l; s_out = out.a1 --
__global__ void node_fin_kernel(const float* __restrict__ bl,
                                const float* __restrict__ watt,
                                float* __restrict__ out, int N) {
    int t = blockIdx.x * blockDim.x + threadIdx.x;
    int n = t >> 4;
    if (n >= N) return;
    int l = t & 15;
    float inv = 1.0f / fmaxf(g_cnt[n], 1.0f);
    float4 a = ((const float4*)(g_agg + (size_t)n * 64))[l];
    float4 o = ((const float4*)(out   + (size_t)n * 64))[l];
    float4 b = ((const float4*)bl)[l];
    o.x = fmaf(a.x, inv, o.x) + b.x;
    o.y = fmaf(a.y, inv, o.y) + b.y;
    o.z = fmaf(a.z, inv, o.z) + b.z;
    o.w = fmaf(a.w, inv, o.w) + b.w;
    ((float4*)(out + (size_t)n * 64))[l] = o;
    float4 w = ((const float4*)watt)[l];        // W_att[0:64]
    float p = o.x * w.x + o.y * w.y + o.z * w.z + o.w * w.w;
    p += __shfl_xor_sync(0xffffffffu, p, 1);
    p += __shfl_xor_sync(0xffffffffu, p, 2);
    p += __shfl_xor_sync(0xffffffffu, p, 4);
    p += __shfl_xor_sync(0xffffffffu, p, 8);
    if (l == 0) g_sout[n] = p;
}

// ---------------- K4: per-edge e = ea@W_e + b_e; att; scatter att*e -------
// Warp per edge; W_e held in registers (2 cols/lane); ea broadcast via shfl.
__global__ void __launch_bounds__(128, 4)
edge_attn_kernel(const int* __restrict__ ei,
                 const float* __restrict__ ea,
                 const float* __restrict__ We,
                 const float* __restrict__ be,
                 const float* __restrict__ watt,
                 const float* __restrict__ batt,
                 float* __restrict__ out, int E) {
    int lane = threadIdx.x & 31;
    int w0 = (blockIdx.x * blockDim.x + threadIdx.x) >> 5;
    int nw = (gridDim.x * blockDim.x) >> 5;

    float2 w[32];
    #pragma unroll
    for (int k = 0; k < 32; k++)
        w[k] = *(const float2*)(We + k * 64 + 2 * lane);
    float2 b2 = *(const float2*)(be + 2 * lane);
    float2 a2 = *(const float2*)(watt + 64 + 2 * lane);   // W_att[64:128]
    float ba = batt[0];

    for (int e = w0; e < E; e += nw) {
        float eav = __ldg(ea + (size_t)e * 32 + lane);
        float acc0 = b2.x, acc1 = b2.y;
        #pragma unroll
        for (int k = 0; k < 32; k++) {
            float ek = __shfl_sync(0xffffffffu, eav, k);
            acc0 = fmaf(ek, w[k].x, acc0);
            acc1 = fmaf(ek, w[k].y, acc1);
        }
        float p = acc0 * a2.x + acc1 * a2.y;
        #pragma unroll
        for (int s = 16; s > 0; s >>= 1)
            p += __shfl_xor_sync(0xffffffffu, p, s);
        int c = __ldg(ei + E + e);
        float z = p + g_sout[c] + ba;
        float att = 1.0f / (1.0f + __expf(-z));
        float v0 = att * acc0, v1 = att * acc1;
        float* dst = out + (size_t)c * 64 + 2 * lane;
        asm volatile("red.global.add.v2.f32 [%0], {%1,%2};"
                     :: "l"(dst), "f"(v0), "f"(v1) : "memory");
    }
}

// ---------------- K5: BN batch statistics ---------------------------------
__global__ void bn_stats_kernel(const float* __restrict__ out, int N) {
    int ch  = threadIdx.x & 63;
    int grp = threadIdx.x >> 6;          // 0..3
    float s = 0.f, q = 0.f;
    for (int n = blockIdx.x * 4 + grp; n < N; n += gridDim.x * 4) {
        float v = out[(size_t)n * 64 + ch];
        s += v;
        q = fmaf(v, v, q);
    }
    __shared__ float sh[8][64];
    sh[grp][ch]     = s;
    sh[4 + grp][ch] = q;
    __syncthreads();
    if (threadIdx.x < 64) {
        float S = 0.f, Q = 0.f;
        #pragma unroll
        for (int g = 0; g < 4; g++) { S += sh[g][threadIdx.x]; Q += sh[4 + g][threadIdx.x]; }
        atomicAdd(g_sums + threadIdx.x, S);
        atomicAdd(g_sums + 64 + threadIdx.x, Q);
    }
}

// ---------------- K5b: fold BN + residual-double into scale/shift ---------
// relu(2*(gamma*(v-mu)*rsqrt(var+eps)+beta)) = relu(v*sc + sf)
__global__ void bn_coef_kernel(const float* __restrict__ gamma,
                               const float* __restrict__ beta, float invN) {
    int c = threadIdx.x;
    float mu  = g_sums[c] * invN;
    float var = g_sums[64 + c] * invN - mu * mu;
    float r = rsqrtf(var + 1e-5f);
    float g = gamma[c];
    g_coef[c] = make_float2(2.0f * g * r, 2.0f * (beta[c] - g * mu * r));
}

// ---------------- K6: apply -----------------------------------------------
__global__ void bn_apply_kernel(float* __restrict__ out, int total) {
    int i = blockIdx.x * blockDim.x + threadIdx.x;
    if (i >= total) return;
    float2 cs = g_coef[i & 63];
    out[i] = fmaxf(fmaf(out[i], cs.x, cs.y), 0.0f);
}

// ---------------- launch ---------------------------------------------------
extern "C" void kernel_launch(void* const* d_in, const int* in_sizes, int n_in,
                              void* d_out, int out_size) {
    const float* x     = (const float*)d_in[0];
    const int*   ei    = (const int*)  d_in[1];
    const float* ea    = (const float*)d_in[2];
    const float* Wl    = (const float*)d_in[3];
    const float* bl    = (const float*)d_in[4];
    const float* Wr    = (const float*)d_in[5];
    const float* We    = (const float*)d_in[6];
    const float* be    = (const float*)d_in[7];
    const float* watt  = (const float*)d_in[8];
    const float* batt  = (const float*)d_in[9];
    const float* gamma = (const float*)d_in[10];
    const float* beta  = (const float*)d_in[11];
    float* out = (float*)d_out;

    int N = in_sizes[0] / 128;   // 100000
    int E = in_sizes[1] / 2;     // 1000000

    cudaFuncSetAttribute(node_gemm_kernel,
                         cudaFuncAttributeMaxDynamicSharedMemorySize, 98304);

    zero_kernel<<<(N * 64 + 255) / 256, 256>>>(N * 64, N);
    node_gemm_kernel<<<(N + 63) / 64, 256, 98304>>>(x, Wl, Wr, out, N);
    edge_agg_kernel<<<(E * 16 + 255) / 256, 256>>>(ei, E);
    node_fin_kernel<<<(N * 16 + 255) / 256, 256>>>(bl, watt, out, N);
    edge_attn_kernel<<<1184, 128>>>(ei, ea, We, be, watt, batt, out, E);
    bn_stats_kernel<<<592, 256>>>(out, N);
    bn_coef_kernel<<<1, 64>>>(gamma, beta, 1.0f / (float)N);
    bn_apply_kernel<<<(N * 64 + 255) / 256, 256>>>(out, N * 64);
}

// round 4
// speedup vs baseline: 2.5408x; 2.5408x over previous
#include <cuda_runtime.h>
#include <math.h>

// Problem constants (shapes fixed for this problem instance)
#define NN 100000
#define NE 1000000

// ---------------- scratch (static device globals; no allocation) ----------
__device__ float g_xl  [NN * 64];   // x @ W_l
__device__ float g_agg [NN * 64];   // segment_sum(xl[row]) into col
__device__ float g_cnt [NN];        // in-degree
__device__ float g_sout[NN];        // dot(out[n], W_att[0:64])
__device__ float g_Z   [NN * 32];   // sum_e att_e * ea_e  (per target node)
__device__ float g_asum[NN];        // sum_e att_e
__device__ float g_wc  [32];        // W_e @ W_att[64:128]
__device__ float g_c0;              // b_e . W_att[64:128] + b_att
__device__ float g_sums[128];       // [0:64) sum, [64:128) sumsq
__device__ float2 g_coef[64];       // fused BN*2 scale/shift

// ---------------- packed f32x2 helpers -------------------------------------
__device__ __forceinline__ unsigned long long pk2(float a, float b) {
    unsigned long long r;
    asm("mov.b64 %0, {%1, %2};" : "=l"(r) : "f"(a), "f"(b));
    return r;
}
__device__ __forceinline__ void ffma2(unsigned long long& d,
                                      unsigned long long a,
                                      unsigned long long b) {
    asm("fma.rn.f32x2 %0, %1, %2, %0;" : "+l"(d) : "l"(a), "l"(b));
}
__device__ __forceinline__ float lo32(unsigned long long v) {
    return __uint_as_float((unsigned)(v & 0xffffffffu));
}
__device__ __forceinline__ float hi32(unsigned long long v) {
    return __uint_as_float((unsigned)(v >> 32));
}

// ---------------- K0: zero scratch ----------------------------------------
__global__ void zero_kernel(int N) {
    int i = blockIdx.x * blockDim.x + threadIdx.x;
    if (i < N * 64) g_agg[i] = 0.0f;
    if (i < N * 32) g_Z[i]   = 0.0f;
    if (i < N)    { g_cnt[i] = 0.0f; g_asum[i] = 0.0f; }
    if (i < 128)    g_sums[i] = 0.0f;
}

// ---------------- Kp: prep wc = W_e @ a2, c0 = b_e.a2 + b_att --------------
__global__ void prep_kernel(const float* __restrict__ We,
                            const float* __restrict__ be,
                            const float* __restrict__ watt,
                            const float* __restrict__ batt) {
    int l = threadIdx.x;  // 32 threads
    float s = 0.f;
    #pragma unroll
    for (int j = 0; j < 64; j++) s = fmaf(We[l * 64 + j], watt[64 + j], s);
    g_wc[l] = s;
    float c = be[l] * watt[64 + l] + be[l + 32] * watt[64 + l + 32];
    #pragma unroll
    for (int o = 16; o > 0; o >>= 1) c += __shfl_xor_sync(0xffffffffu, c, o);
    if (l == 0) g_c0 = c + batt[0];
}

// ---------------- K1: fused node GEMM: xl = x@W_l, out = x@W_r (f32x2) -----
__global__ void node_gemm_kernel(const float* __restrict__ x,
                                 const float* __restrict__ Wl,
                                 const float* __restrict__ Wr,
                                 float* __restrict__ out, int N) {
    extern __shared__ float sm[];
    float* Wc = sm;                                   // 128x128 = 64KB
    const int tid  = threadIdx.x;
    const int lane = tid & 31;
    const int wid  = tid >> 5;
    float* xs = sm + 128 * 128 + wid * (8 * 128);     // 8 rows x 128 per warp

    for (int i = tid; i < 128 * 64; i += blockDim.x) {
        int k = i >> 6, j = i & 63;
        Wc[k * 128 + j]      = Wl[i];
        Wc[k * 128 + 64 + j] = Wr[i];
    }
    __syncthreads();

    int base = (blockIdx.x * 8 + wid) * 8;            // N % 8 == 0
    if (base >= N) return;

    const float4* xg = (const float4*)(x + (size_t)base * 128);
    #pragma unroll
    for (int i = 0; i < 8; i++)
        ((float4*)xs)[lane + 32 * i] = xg[lane + 32 * i];
    __syncwarp();

    unsigned long long acc[8][2];
    #pragma unroll
    for (int r = 0; r < 8; r++) { acc[r][0] = 0ull; acc[r][1] = 0ull; }

    #pragma unroll 4
    for (int k = 0; k < 128; k++) {
        ulonglong2 wv = *(const ulonglong2*)(Wc + k * 128 + lane * 4);
        #pragma unroll
        for (int r = 0; r < 8; r++) {
            unsigned long long xx = pk2(xs[r * 128 + k], xs[r * 128 + k]);
            ffma2(acc[r][0], xx, wv.x);
            ffma2(acc[r][1], xx, wv.y);
        }
    }

    #pragma unroll
    for (int r = 0; r < 8; r++) {
        int row = base + r;
        ulonglong2 v; v.x = acc[r][0]; v.y = acc[r][1];
        if (lane < 16)
            *(ulonglong2*)(g_xl + (size_t)row * 64 + lane * 4) = v;
        else
            *(ulonglong2*)(out + (size_t)row * 64 + (lane - 16) * 4) = v;
    }
}

// ---------------- K2: edge aggregation: agg[col] += xl[row], cnt[col]++ ----
__global__ void edge_agg_kernel(const int* __restrict__ ei, int E) {
    int t = blockIdx.x * blockDim.x + threadIdx.x;
    int e = t >> 4;
    if (e >= E) return;
    int l = t & 15;
    int r = __ldg(ei + e);
    int c = __ldg(ei + E + e);
    float4 v = ((const float4*)(g_xl + (size_t)r * 64))[l];
    float* dst = g_agg + (size_t)c * 64 + l * 4;
    asm volatile("red.global.add.v4.f32 [%0], {%1,%2,%3,%4};"
                 :: "l"(dst), "f"(v.x), "f"(v.y), "f"(v.z), "f"(v.w)
                 : "memory");
    if (l == 0) atomicAdd(g_cnt + c, 1.0f);
}

// ---------------- K3: out = agg/max(cnt,1) + x@W_r + b_l; s_out ------------
__global__ void node_fin_kernel(const float* __restrict__ bl,
                                const float* __restrict__ watt,
                                float* __restrict__ out, int N) {
    int t = blockIdx.x * blockDim.x + threadIdx.x;
    int n = t >> 4;
    if (n >= N) return;
    int l = t & 15;
    float inv = 1.0f / fmaxf(g_cnt[n], 1.0f);
    float4 a = ((const float4*)(g_agg + (size_t)n * 64))[l];
    float4 o = ((const float4*)(out   + (size_t)n * 64))[l];
    float4 b = ((const float4*)bl)[l];
    o.x = fmaf(a.x, inv, o.x) + b.x;
    o.y = fmaf(a.y, inv, o.y) + b.y;
    o.z = fmaf(a.z, inv, o.z) + b.z;
    o.w = fmaf(a.w, inv, o.w) + b.w;
    ((float4*)(out + (size_t)n * 64))[l] = o;
    float4 w = ((const float4*)watt)[l];        // W_att[0:64]
    float p = o.x * w.x + o.y * w.y + o.z * w.z + o.w * w.w;
    p += __shfl_xor_sync(0xffffffffu, p, 1);
    p += __shfl_xor_sync(0xffffffffu, p, 2);
    p += __shfl_xor_sync(0xffffffffu, p, 4);
    p += __shfl_xor_sync(0xffffffffu, p, 8);
    if (l == 0) g_sout[n] = p;
}

// ---------------- K4: edge attention scatter (factored) --------------------
// att_e = sigmoid(ea_e . wc + s_out[col] + c0); Z[col] += att*ea; asum[col]+=att
// 8 lanes per edge, float4 per lane.
__global__ void edge_att_kernel(const int* __restrict__ ei,
                                const float* __restrict__ ea, int E) {
    int t = blockIdx.x * blockDim.x + threadIdx.x;
    int e = t >> 3;
    if (e >= E) return;
    int l = t & 7;
    float4 a = __ldg((const float4*)(ea + (size_t)e * 32) + l);
    float4 w = ((const float4*)g_wc)[l];
    float p = a.x * w.x + a.y * w.y + a.z * w.z + a.w * w.w;
    p += __shfl_xor_sync(0xffffffffu, p, 1);
    p += __shfl_xor_sync(0xffffffffu, p, 2);
    p += __shfl_xor_sync(0xffffffffu, p, 4);
    int c = __ldg(ei + E + e);
    float z = p + g_sout[c] + g_c0;
    float att = 1.0f / (1.0f + __expf(-z));
    float* dst = g_Z + (size_t)c * 32 + l * 4;
    asm volatile("red.global.add.v4.f32 [%0], {%1,%2,%3,%4};"
                 :: "l"(dst), "f"(att * a.x), "f"(att * a.y),
                    "f"(att * a.z), "f"(att * a.w)
                 : "memory");
    if (l == 0) atomicAdd(g_asum + c, att);
}

// ---------------- K5: out += Z@W_e + asum*b_e; accumulate BN stats ---------
// Warp per node (grid-strided). W_e in regs (2 cols/lane, packed f32x2).
__global__ void __launch_bounds__(256)
node_out2_kernel(const float* __restrict__ We,
                 const float* __restrict__ be,
                 float* __restrict__ out, int N) {
    int lane = threadIdx.x & 31;
    int gw = (blockIdx.x * blockDim.x + threadIdx.x) >> 5;
    int nw = (gridDim.x * blockDim.x) >> 5;

    unsigned long long w[32];
    #pragma unroll
    for (int k = 0; k < 32; k++)
        w[k] = *(const unsigned long long*)(We + k * 64 + 2 * lane);
    unsigned long long beu = *(const unsigned long long*)(be + 2 * lane);

    float s0 = 0.f, q0 = 0.f, s1 = 0.f, q1 = 0.f;
    for (int n = gw; n < N; n += nw) {
        float zl = g_Z[(size_t)n * 32 + lane];
        float as = __ldg(g_asum + n);
        unsigned long long acc =
            *(const unsigned long long*)(out + (size_t)n * 64 + 2 * lane);
        ffma2(acc, pk2(as, as), beu);
        #pragma unroll
        for (int k = 0; k < 32; k++) {
            float ek = __shfl_sync(0xffffffffu, zl, k);
            ffma2(acc, pk2(ek, ek), w[k]);
        }
        *(unsigned long long*)(out + (size_t)n * 64 + 2 * lane) = acc;
        float v0 = lo32(acc), v1 = hi32(acc);
        s0 += v0; q0 = fmaf(v0, v0, q0);
        s1 += v1; q1 = fmaf(v1, v1, q1);
    }

    __shared__ float ss[64], sq[64];
    if (threadIdx.x < 64) { ss[threadIdx.x] = 0.f; sq[threadIdx.x] = 0.f; }
    __syncthreads();
    atomicAdd(&ss[2 * lane],     s0);
    atomicAdd(&ss[2 * lane + 1], s1);
    atomicAdd(&sq[2 * lane],     q0);
    atomicAdd(&sq[2 * lane + 1], q1);
    __syncthreads();
    if (threadIdx.x < 64) {
        atomicAdd(g_sums + threadIdx.x,      ss[threadIdx.x]);
        atomicAdd(g_sums + 64 + threadIdx.x, sq[threadIdx.x]);
    }
}

// ---------------- K5b: fold BN + residual-double into scale/shift ----------
__global__ void bn_coef_kernel(const float* __restrict__ gamma,
                               const float* __restrict__ beta, float invN) {
    int c = threadIdx.x;
    float mu  = g_sums[c] * invN;
    float var = g_sums[64 + c] * invN - mu * mu;
    float r = rsqrtf(var + 1e-5f);
    float g = gamma[c];
    g_coef[c] = make_float2(2.0f * g * r, 2.0f * (beta[c] - g * mu * r));
}

// ---------------- K6: apply -------------------------------------------------
__global__ void bn_apply_kernel(float* __restrict__ out, int total) {
    int i = blockIdx.x * blockDim.x + threadIdx.x;
    if (i >= total) return;
    float2 cs = g_coef[i & 63];
    out[i] = fmaxf(fmaf(out[i], cs.x, cs.y), 0.0f);
}

// ---------------- launch ----------------------------------------------------
extern "C" void kernel_launch(void* const* d_in, const int* in_sizes, int n_in,
                              void* d_out, int out_size) {
    const float* x     = (const float*)d_in[0];
    const int*   ei    = (const int*)  d_in[1];
    const float* ea    = (const float*)d_in[2];
    const float* Wl    = (const float*)d_in[3];
    const float* bl    = (const float*)d_in[4];
    const float* Wr    = (const float*)d_in[5];
    const float* We    = (const float*)d_in[6];
    const float* be    = (const float*)d_in[7];
    const float* watt  = (const float*)d_in[8];
    const float* batt  = (const float*)d_in[9];
    const float* gamma = (const float*)d_in[10];
    const float* beta  = (const float*)d_in[11];
    float* out = (float*)d_out;

    int N = in_sizes[0] / 128;   // 100000
    int E = in_sizes[1] / 2;     // 1000000

    cudaFuncSetAttribute(node_gemm_kernel,
                         cudaFuncAttributeMaxDynamicSharedMemorySize, 98304);

    zero_kernel<<<(N * 64 + 255) / 256, 256>>>(N);
    prep_kernel<<<1, 32>>>(We, be, watt, batt);
    node_gemm_kernel<<<(N + 63) / 64, 256, 98304>>>(x, Wl, Wr, out, N);
    edge_agg_kernel<<<(E * 16 + 255) / 256, 256>>>(ei, E);
    node_fin_kernel<<<(N * 16 + 255) / 256, 256>>>(bl, watt, out, N);
    edge_att_kernel<<<(E * 8 + 255) / 256, 256>>>(ei, ea, E);
    node_out2_kernel<<<1184, 256>>>(We, be, out, N);
    bn_coef_kernel<<<1, 64>>>(gamma, beta, 1.0f / (float)N);
    bn_apply_kernel<<<(N * 64 + 255) / 256, 256>>>(out, N * 64);
}